// round 8
// baseline (speedup 1.0000x reference)
#include <cuda_runtime.h>
#include <cuda_bf16.h>
#include <cstdint>
#include <math.h>

#define BB 4
#define SS 1024
#define EE 768
#define HH 12
#define DD 64
#define MT (BB*SS)
#define SCALING 0.125f

// ---------------- device scratch (allocation-free rule) ----------------
__device__ __nv_bfloat16 g_Qhi[BB*HH*SS*DD], g_Qlo[BB*HH*SS*DD];
__device__ __nv_bfloat16 g_Khi[BB*HH*SS*DD], g_Klo[BB*HH*SS*DD];
__device__ __nv_bfloat16 g_Vhi[BB*HH*SS*DD], g_Vlo[BB*HH*SS*DD];
__device__ __nv_bfloat16 g_Xhi[MT*EE],  g_Xlo[MT*EE];
__device__ __nv_bfloat16 g_Whi[4*EE*EE], g_Wlo[4*EE*EE];
__device__ __nv_bfloat16 g_AOhi[MT*EE], g_AOlo[MT*EE];

__device__ __forceinline__ uint32_t smem_u32(const void* p) {
    uint32_t a;
    asm("{ .reg .u64 t; cvta.to.shared.u64 t, %1; cvt.u32.u64 %0, t; }"
        : "=r"(a) : "l"(p));
    return a;
}

#define LDSM4(r, addr) \
    asm volatile("ldmatrix.sync.aligned.m8n8.x4.shared.b16 {%0,%1,%2,%3}, [%4];" \
        : "=r"((r)[0]), "=r"((r)[1]), "=r"((r)[2]), "=r"((r)[3]) : "r"(addr))
#define LDSM4T(r, addr) \
    asm volatile("ldmatrix.sync.aligned.m8n8.x4.trans.shared.b16 {%0,%1,%2,%3}, [%4];" \
        : "=r"((r)[0]), "=r"((r)[1]), "=r"((r)[2]), "=r"((r)[3]) : "r"(addr))

#define MMA_BF16(d, a, b0v, b1v) \
    asm volatile("mma.sync.aligned.m16n8k16.row.col.f32.bf16.bf16.f32 " \
        "{%0,%1,%2,%3}, {%4,%5,%6,%7}, {%8,%9}, {%0,%1,%2,%3};" \
        : "+f"((d)[0]), "+f"((d)[1]), "+f"((d)[2]), "+f"((d)[3]) \
        : "r"((a)[0]), "r"((a)[1]), "r"((a)[2]), "r"((a)[3]), "r"(b0v), "r"(b1v))

#define CP_ASYNC16(smem, gmem) \
    asm volatile("cp.async.cg.shared.global [%0], [%1], 16;" :: "r"(smem), "l"(gmem))
#define CP_COMMIT()  asm volatile("cp.async.commit_group;" ::: "memory")
#define CP_WAIT0()   asm volatile("cp.async.wait_group 0;" ::: "memory")
#define CP_WAIT1()   asm volatile("cp.async.wait_group 1;" ::: "memory")

// pack 2 fp32 -> bf16x2 hi + bf16x2 lo (3-split residual), cvt.bf16x2 fast path
__device__ __forceinline__ void splitpack(float x, float y, uint32_t& hi, uint32_t& lo) {
    asm("cvt.rn.bf16x2.f32 %0, %1, %2;" : "=r"(hi) : "f"(y), "f"(x));
    float hx = __uint_as_float(hi << 16);
    float hy = __uint_as_float(hi & 0xffff0000u);
    float lx = x - hx, ly = y - hy;
    asm("cvt.rn.bf16x2.f32 %0, %1, %2;" : "=r"(lo) : "f"(ly), "f"(lx));
}

// ---------------------------------------------------------------------------
// merged fp32 -> (bf16 hi, lo) split: blocks [0,3072) = X, then 4x576 = W slots
// ---------------------------------------------------------------------------
__global__ void __launch_bounds__(256) split_all_kernel(
    const float* __restrict__ X,
    const float* __restrict__ qw, const float* __restrict__ kw,
    const float* __restrict__ vw, const float* __restrict__ ow)
{
    const int bid = blockIdx.x;
    const float* src;
    __nv_bfloat16 *dhi, *dlo;
    size_t off;
    if (bid < 3072) {
        src = X; dhi = g_Xhi; dlo = g_Xlo;
        off = (size_t)bid * 1024;
    } else {
        int r = bid - 3072;
        int slot = r / 576, rb = r % 576;
        src = (slot == 0) ? qw : (slot == 1) ? kw : (slot == 2) ? vw : ow;
        dhi = g_Whi + (size_t)slot * EE * EE;
        dlo = g_Wlo + (size_t)slot * EE * EE;
        off = (size_t)rb * 1024;
    }
    size_t i = off + threadIdx.x * 4;
    float4 v = *(const float4*)(src + i);
    float xs[4] = {v.x, v.y, v.z, v.w};
    #pragma unroll
    for (int j = 0; j < 4; j++) {
        __nv_bfloat16 hv = __float2bfloat16(xs[j]);
        dhi[i+j] = hv;
        dlo[i+j] = __float2bfloat16(xs[j] - __bfloat162float(hv));
    }
}

// ---------------------------------------------------------------------------
// HMMA GEMM: D = A(M,K) @ W(N,K)^T via 3x bf16-split mma.sync, fp32 accum.
// CTA tile TMROWS x 128, 512 threads, 16 warps (4x4), warp tile (TMROWS/4) x 32.
// BK=32, 3-stage cp.async pipeline. launch_bounds(512,1): 128-reg cap with
// ~40 regs of scheduler slack (acc is only NT*16 regs).
// Rows are 64B; swizzle: chunk16B ^= ((row>>1)&3).
// ---------------------------------------------------------------------------
#define NSTG (EE/32)   // 24 K-stages
template<int TMROWS>
__global__ void __launch_bounds__(512, 1) gemm_mma_kernel(
    const float* __restrict__ b0p, const float* __restrict__ b1p,
    const float* __restrict__ b2p, float* __restrict__ outp,
    int wslot0, int is_qkv)
{
    extern __shared__ char dsm[];
    const uint32_t sbase = smem_u32(dsm);
    constexpr int NT = TMROWS / 64;                 // m-frags (16 rows) per warp
    constexpr uint32_t ASZ = (uint32_t)TMROWS * 64; // bytes per A tile
    constexpr uint32_t STAGE = 2*ASZ + 16384u;      // Ahi,Alo,Bhi,Blo

    const int tid = threadIdx.x;
    const int wid = tid >> 5, lane = tid & 31;
    const int warp_m = wid & 3, warp_n = wid >> 2;
    const int m0w = warp_m * (TMROWS/4), n0w = warp_n * 32;

    const int z = is_qkv ? blockIdx.z : 0;
    const size_t woff = (size_t)(wslot0 + z) * EE * EE;
    const float* bias = (z == 0) ? b0p : (z == 1) ? b1p : b2p;
    const float scale = (is_qkv && z == 0) ? SCALING : 1.0f;
    __nv_bfloat16* outHi = (z == 0) ? g_Qhi : (z == 1) ? g_Khi : g_Vhi;
    __nv_bfloat16* outLo = (z == 0) ? g_Qlo : (z == 1) ? g_Klo : g_Vlo;

    const int n0 = blockIdx.x * 128;
    const int m0 = blockIdx.y * TMROWS;

    const __nv_bfloat16* s0 = (is_qkv ? g_Xhi : g_AOhi) + (size_t)m0 * EE;
    const __nv_bfloat16* s1 = (is_qkv ? g_Xlo : g_AOlo) + (size_t)m0 * EE;
    const __nv_bfloat16* s2 = g_Whi + woff + (size_t)n0 * EE;
    const __nv_bfloat16* s3 = g_Wlo + woff + (size_t)n0 * EE;

    // loader: A tiles TMROWS rows x 4 chunks; B tiles 128 rows x 4 chunks.
    const int lrow = tid >> 2;           // 0..127
    const int lch  = tid & 3;            // chunk 0..3
    const uint32_t lsw = (uint32_t)(lrow * 64 + ((lch ^ ((lrow >> 1) & 3)) << 4));
    auto stage_load = [&](int k0, int stg) {
        uint32_t sb = sbase + (uint32_t)stg * STAGE;
        const size_t goff = (size_t)lrow * EE + k0 + lch*8;
        if (TMROWS == 128 || tid < TMROWS*4) {
            CP_ASYNC16(sb + lsw,       s0 + goff);
            CP_ASYNC16(sb + ASZ + lsw, s1 + goff);
        }
        CP_ASYNC16(sb + 2*ASZ + lsw,         s2 + goff);
        CP_ASYNC16(sb + 2*ASZ + 8192u + lsw, s3 + goff);
        CP_COMMIT();
    };

    const int l7 = lane & 7;
    const int arow_sw = (lane >> 1) & 3;
    const int brow7 = l7 + ((lane >> 4) << 3);
    const int brow_sw = (brow7 >> 1) & 3;
    uint32_t aoff[NT], boff[2];
    #pragma unroll
    for (int t = 0; t < NT; t++)
        aoff[t] = (uint32_t)(m0w + t*16 + (lane & 15)) * 64u;
    #pragma unroll
    for (int p = 0; p < 2; p++)
        boff[p] = (uint32_t)(n0w + p*16 + brow7) * 64u;
    const int achk = lane >> 4;
    const int bchk = (lane >> 3) & 1;

    float acc[NT][4][4] = {};

    stage_load(0, 0);
    stage_load(32, 1);

    #pragma unroll 1
    for (int s = 0; s < NSTG; s++) {
        if (s == NSTG - 1) { CP_WAIT0(); } else { CP_WAIT1(); }
        __syncthreads();
        if (s + 2 < NSTG) stage_load((s + 2) * 32, (s + 2) % 3);

        const uint32_t stg = sbase + (uint32_t)(s % 3) * STAGE;
        const uint32_t Ahi = stg, Alo = stg + ASZ;
        const uint32_t Bhi = stg + 2*ASZ, Blo = stg + 2*ASZ + 8192u;

        #pragma unroll
        for (int ks = 0; ks < 2; ks++) {
            const uint32_t asw = (uint32_t)((2*ks + achk) ^ arow_sw) << 4;
            const uint32_t bsw = (uint32_t)((2*ks + bchk) ^ brow_sw) << 4;
            uint32_t Bh[2][4], Bl[2][4];
            #pragma unroll
            for (int p = 0; p < 2; p++) {
                LDSM4(Bh[p], Bhi + boff[p] + bsw);
                LDSM4(Bl[p], Blo + boff[p] + bsw);
            }
            #pragma unroll
            for (int t = 0; t < NT; t++) {
                uint32_t Ah[4], Al[4];
                LDSM4(Ah, Ahi + aoff[t] + asw);
                LDSM4(Al, Alo + aoff[t] + asw);
                #pragma unroll
                for (int n = 0; n < 4; n++) {
                    const int p = n >> 1, q = (n & 1) * 2;
                    MMA_BF16(acc[t][n], Ah, Bh[p][q], Bh[p][q+1]);
                    MMA_BF16(acc[t][n], Ah, Bl[p][q], Bl[p][q+1]);
                    MMA_BF16(acc[t][n], Al, Bh[p][q], Bh[p][q+1]);
                }
            }
        }
    }

    // epilogue
    const int rl = lane >> 2, cl2 = (lane & 3) * 2;
    #pragma unroll
    for (int t = 0; t < NT; t++)
        #pragma unroll
        for (int n = 0; n < 4; n++) {
            const int col = n0 + n0w + n*8 + cl2;
            #pragma unroll
            for (int half = 0; half < 2; half++) {
                const int row = m0 + m0w + t*16 + rl + half*8;
                float ox = (acc[t][n][half*2+0] + bias[col+0]) * scale;
                float oy = (acc[t][n][half*2+1] + bias[col+1]) * scale;
                if (is_qkv) {
                    const int hh = col >> 6, d0 = col & 63;
                    const int bb_ = row >> 10, ss_ = row & 1023;
                    size_t idx = ((size_t)((bb_*HH + hh)*SS + ss_))*DD + d0;
                    uint32_t hi, lo;
                    splitpack(ox, oy, hi, lo);
                    *(uint32_t*)(outHi + idx) = hi;
                    *(uint32_t*)(outLo + idx) = lo;
                } else {
                    float2 o; o.x = ox; o.y = oy;
                    *(float2*)(outp + (size_t)row * EE + col) = o;
                }
            }
        }
}

// ---------------------------------------------------------------------------
// Flash attention on mma.sync bf16 (3-split). CTA = 128 Q rows x (b,h).
// 8 warps, warp = m16 x n64. K/V chunks of 64 rows, double-buffered cp.async.
// Smem: Q stage 32KB | 2 KV stages (Khi,Klo,Vhi,Vlo; 8KB each) | pk[1024].
// launch_bounds(256,2): cap regs at 128 so 2 CTAs/SM co-reside.
// ---------------------------------------------------------------------------
__global__ void __launch_bounds__(256, 2) attn_mma_kernel(
    const int* __restrict__ pos_row, const int* __restrict__ pos_col,
    const float* __restrict__ rel_table)
{
    extern __shared__ char dsm[];
    const uint32_t sbase = smem_u32(dsm);
    const uint32_t sQhi = sbase, sQlo = sbase + 16384u;
    int* pk = (int*)(dsm + 98304);

    const int tid = threadIdx.x;
    const int wid = tid >> 5, lane = tid & 31;
    const int l7 = lane & 7;
    const int rl = lane >> 2, cl2 = (lane & 3) * 2;
    const int achk = lane >> 4;
    const int bchk = (lane >> 3) & 1;

    const int q0 = blockIdx.x * 128;
    const int h = blockIdx.y, b = blockIdx.z;
    const size_t hb = (size_t)(b*HH + h) * SS * DD;

    #pragma unroll
    for (int i = 0; i < 4; i++) {
        int s = tid + i*256;
        pk[s] = (pos_row[b*SS + s] << 5) | pos_col[b*SS + s];
    }

    // Q stage: 128 rows x 64 bf16 hi/lo (group 0)
    {
        const int half = tid >> 7, r = tid & 127;
        const __nv_bfloat16* src = (half ? g_Qlo : g_Qhi) + hb + (size_t)(q0 + r)*DD;
        uint32_t dstrow = (half ? sQlo : sQhi) + (uint32_t)r * 128u;
        #pragma unroll
        for (int ch = 0; ch < 8; ch++)
            CP_ASYNC16(dstrow + ((ch ^ (r & 7)) << 4), src + ch*8);
        CP_COMMIT();
    }

    auto kv_load = [&](int kb, int stg) {
        const int t = tid >> 6, r = tid & 63;
        const __nv_bfloat16* src =
            (t==0 ? g_Khi : t==1 ? g_Klo : t==2 ? g_Vhi : g_Vlo)
            + hb + (size_t)(kb + r)*DD;
        uint32_t dstrow = sbase + 32768u + (uint32_t)stg*32768u
                        + (uint32_t)t*8192u + (uint32_t)r*128u;
        #pragma unroll
        for (int ch = 0; ch < 8; ch++)
            CP_ASYNC16(dstrow + ((ch ^ (r & 7)) << 4), src + ch*8);
        CP_COMMIT();
    };
    kv_load(0, 0);

    CP_WAIT1();
    __syncthreads();

    uint32_t qh[4][4], ql[4][4];
    const uint32_t aq = (uint32_t)(wid*16 + (lane & 15)) * 128u;
    #pragma unroll
    for (int ks = 0; ks < 4; ks++) {
        uint32_t sw = (uint32_t)((2*ks + achk) ^ l7) << 4;
        LDSM4(qh[ks], sQhi + aq + sw);
        LDSM4(ql[ks], sQlo + aq + sw);
    }

    const int rq0 = pk[q0 + wid*16 + rl];
    const int rq1 = pk[q0 + wid*16 + rl + 8];
    const float tb0 = rel_table[0*HH + h];
    const float tb1 = rel_table[1*HH + h];
    const float tb2 = rel_table[2*HH + h];
    const float tb3 = rel_table[3*HH + h];

    float oacc[8][4] = {};
    float m0 = -1e30f, m1 = -1e30f, l0 = 0.f, l1 = 0.f;

    #pragma unroll 1
    for (int kt = 0; kt < SS/64; kt++) {
        CP_WAIT0();
        __syncthreads();
        if (kt + 1 < SS/64) kv_load((kt + 1) * 64, (kt + 1) & 1);

        const uint32_t st  = sbase + 32768u + (uint32_t)(kt & 1) * 32768u;
        const uint32_t Khi = st, Klo = st + 8192u;
        const uint32_t Vhi = st + 16384u, Vlo = st + 24576u;

        // S = Q K^T  (m16 x n64), fp32 accum
        float sacc[8][4] = {};
        #pragma unroll
        for (int ks = 0; ks < 4; ks++) {
            const uint32_t bsw = (uint32_t)((2*ks + bchk) ^ l7) << 4;
            #pragma unroll
            for (int p = 0; p < 4; p++) {
                const uint32_t bo =
                    (uint32_t)(p*16 + l7 + ((lane >> 4) << 3)) * 128u + bsw;
                uint32_t Bh[4], Bl[4];
                LDSM4(Bh, Khi + bo);
                LDSM4(Bl, Klo + bo);
                MMA_BF16(sacc[2*p],   qh[ks], Bh[0], Bh[1]);
                MMA_BF16(sacc[2*p],   qh[ks], Bl[0], Bl[1]);
                MMA_BF16(sacc[2*p],   ql[ks], Bh[0], Bh[1]);
                MMA_BF16(sacc[2*p+1], qh[ks], Bh[2], Bh[3]);
                MMA_BF16(sacc[2*p+1], qh[ks], Bl[2], Bl[3]);
                MMA_BF16(sacc[2*p+1], ql[ks], Bh[2], Bh[3]);
            }
        }

        // bias
        const int kb = kt * 64;
        #pragma unroll
        for (int t = 0; t < 8; t++) {
            int c0 = kb + t*8 + cl2;
            int rk0 = pk[c0], rk1 = pk[c0 + 1];
            int x;
            x = rq0 ^ rk0; sacc[t][0] += (x < 32) ? (((x & 31) == 0) ? tb3 : tb1)
                                                  : (((x & 31) == 0) ? tb2 : tb0);
            x = rq0 ^ rk1; sacc[t][1] += (x < 32) ? (((x & 31) == 0) ? tb3 : tb1)
                                                  : (((x & 31) == 0) ? tb2 : tb0);
            x = rq1 ^ rk0; sacc[t][2] += (x < 32) ? (((x & 31) == 0) ? tb3 : tb1)
                                                  : (((x & 31) == 0) ? tb2 : tb0);
            x = rq1 ^ rk1; sacc[t][3] += (x < 32) ? (((x & 31) == 0) ? tb3 : tb1)
                                                  : (((x & 31) == 0) ? tb2 : tb0);
        }

        // online softmax (MUFU exp; 4 lanes/row)
        float mx0 = sacc[0][0], mx1 = sacc[0][2];
        #pragma unroll
        for (int t = 0; t < 8; t++) {
            mx0 = fmaxf(mx0, fmaxf(sacc[t][0], sacc[t][1]));
            mx1 = fmaxf(mx1, fmaxf(sacc[t][2], sacc[t][3]));
        }
        mx0 = fmaxf(mx0, __shfl_xor_sync(0xffffffffu, mx0, 1));
        mx0 = fmaxf(mx0, __shfl_xor_sync(0xffffffffu, mx0, 2));
        mx1 = fmaxf(mx1, __shfl_xor_sync(0xffffffffu, mx1, 1));
        mx1 = fmaxf(mx1, __shfl_xor_sync(0xffffffffu, mx1, 2));
        float mn0 = fmaxf(m0, mx0), mn1 = fmaxf(m1, mx1);
        float sc0 = __expf(m0 - mn0), sc1 = __expf(m1 - mn1);
        m0 = mn0; m1 = mn1;
        float rs0 = 0.f, rs1 = 0.f;
        #pragma unroll
        for (int t = 0; t < 8; t++) {
            sacc[t][0] = __expf(sacc[t][0] - mn0);
            sacc[t][1] = __expf(sacc[t][1] - mn0);
            sacc[t][2] = __expf(sacc[t][2] - mn1);
            sacc[t][3] = __expf(sacc[t][3] - mn1);
            rs0 += sacc[t][0] + sacc[t][1];
            rs1 += sacc[t][2] + sacc[t][3];
        }
        rs0 += __shfl_xor_sync(0xffffffffu, rs0, 1);
        rs0 += __shfl_xor_sync(0xffffffffu, rs0, 2);
        rs1 += __shfl_xor_sync(0xffffffffu, rs1, 1);
        rs1 += __shfl_xor_sync(0xffffffffu, rs1, 2);
        l0 = l0 * sc0 + rs0;
        l1 = l1 * sc1 + rs1;
        #pragma unroll
        for (int t = 0; t < 8; t++) {
            oacc[t][0] *= sc0; oacc[t][1] *= sc0;
            oacc[t][2] *= sc1; oacc[t][3] *= sc1;
        }

        // O += P V : P fragments straight from sacc (hi/lo split)
        #pragma unroll
        for (int ks = 0; ks < 4; ks++) {
            uint32_t ph[4], pl[4];
            splitpack(sacc[2*ks][0],   sacc[2*ks][1],   ph[0], pl[0]);
            splitpack(sacc[2*ks][2],   sacc[2*ks][3],   ph[1], pl[1]);
            splitpack(sacc[2*ks+1][0], sacc[2*ks+1][1], ph[2], pl[2]);
            splitpack(sacc[2*ks+1][2], sacc[2*ks+1][3], ph[3], pl[3]);
            const uint32_t vr =
                (uint32_t)(ks*16 + l7 + (((lane >> 3) & 1) << 3)) * 128u;
            #pragma unroll
            for (int p = 0; p < 4; p++) {
                const uint32_t vsw = (uint32_t)((2*p + achk) ^ l7) << 4;
                uint32_t Vh[4], Vl[4];
                LDSM4T(Vh, Vhi + vr + vsw);
                LDSM4T(Vl, Vlo + vr + vsw);
                MMA_BF16(oacc[2*p],   ph, Vh[0], Vh[1]);
                MMA_BF16(oacc[2*p],   ph, Vl[0], Vl[1]);
                MMA_BF16(oacc[2*p],   pl, Vh[0], Vh[1]);
                MMA_BF16(oacc[2*p+1], ph, Vh[2], Vh[3]);
                MMA_BF16(oacc[2*p+1], ph, Vl[2], Vl[3]);
                MMA_BF16(oacc[2*p+1], pl, Vh[2], Vh[3]);
            }
        }
    }

    // epilogue: normalize, emit bf16 hi/lo AO at [B,S,E] (e = h*64+d)
    const float inv0 = 1.0f / l0, inv1 = 1.0f / l1;
    const int qrow0 = q0 + wid*16 + rl;
    #pragma unroll
    for (int t = 0; t < 8; t++) {
        const int e = h*64 + t*8 + cl2;
        size_t i0 = (size_t)(b*SS + qrow0) * EE + e;
        size_t i1 = (size_t)(b*SS + qrow0 + 8) * EE + e;
        uint32_t hi, lo;
        splitpack(oacc[t][0] * inv0, oacc[t][1] * inv0, hi, lo);
        *(uint32_t*)(g_AOhi + i0) = hi;
        *(uint32_t*)(g_AOlo + i0) = lo;
        splitpack(oacc[t][2] * inv1, oacc[t][3] * inv1, hi, lo);
        *(uint32_t*)(g_AOhi + i1) = hi;
        *(uint32_t*)(g_AOlo + i1) = lo;
    }
}

// ---------------------------------------------------------------------------
extern "C" void kernel_launch(void* const* d_in, const int* in_sizes, int n_in,
                              void* d_out, int out_size) {
    const float* X  = (const float*)d_in[0];
    const int*   pr = (const int*)  d_in[1];
    const int*   pc = (const int*)  d_in[2];
    const float* qw = (const float*)d_in[3];
    const float* qb = (const float*)d_in[4];
    const float* kw = (const float*)d_in[5];
    const float* kb = (const float*)d_in[6];
    const float* vw = (const float*)d_in[7];
    const float* vb = (const float*)d_in[8];
    const float* ow = (const float*)d_in[9];
    const float* ob = (const float*)d_in[10];
    const float* rt = (const float*)d_in[11];
    float* out = (float*)d_out;

    const int DSMEM_G128 = 3 * 32768;
    const int DSMEM_G64  = 3 * 24576;
    cudaFuncSetAttribute(gemm_mma_kernel<128>,
                         cudaFuncAttributeMaxDynamicSharedMemorySize, DSMEM_G128);
    cudaFuncSetAttribute(gemm_mma_kernel<64>,
                         cudaFuncAttributeMaxDynamicSharedMemorySize, DSMEM_G64);
    const int DSMEM_A = 32768 + 2*32768 + 4096;    // 102400
    cudaFuncSetAttribute(attn_mma_kernel,
                         cudaFuncAttributeMaxDynamicSharedMemorySize, DSMEM_A);

    split_all_kernel<<<3072 + 4*576, 256>>>(X, qw, kw, vw, ow);

    dim3 g1(EE/128, MT/128, 3);
    gemm_mma_kernel<128><<<g1, 512, DSMEM_G128>>>(qb, kb, vb, nullptr, 0, 1);

    dim3 g2(SS/128, HH, BB);
    attn_mma_kernel<<<g2, 256, DSMEM_A>>>(pr, pc, rt);

    dim3 g3(EE/128, MT/64, 1);
    gemm_mma_kernel<64><<<g3, 512, DSMEM_G64>>>(ob, ob, ob, out, 3, 0);
}

// round 9
// speedup vs baseline: 1.0752x; 1.0752x over previous
#include <cuda_runtime.h>
#include <cuda_bf16.h>
#include <cstdint>
#include <math.h>

#define BB 4
#define SS 1024
#define EE 768
#define HH 12
#define DD 64
#define MT (BB*SS)
#define SCALING 0.125f

// ---------------- device scratch (allocation-free rule) ----------------
__device__ __nv_bfloat16 g_Qhi[BB*HH*SS*DD], g_Qlo[BB*HH*SS*DD];
__device__ __nv_bfloat16 g_Khi[BB*HH*SS*DD], g_Klo[BB*HH*SS*DD];
__device__ __nv_bfloat16 g_Vhi[BB*HH*SS*DD], g_Vlo[BB*HH*SS*DD];
__device__ __nv_bfloat16 g_Xhi[MT*EE],  g_Xlo[MT*EE];
__device__ __nv_bfloat16 g_Whi[4*EE*EE], g_Wlo[4*EE*EE];
__device__ __nv_bfloat16 g_AOhi[MT*EE], g_AOlo[MT*EE];

__device__ __forceinline__ uint32_t smem_u32(const void* p) {
    uint32_t a;
    asm("{ .reg .u64 t; cvta.to.shared.u64 t, %1; cvt.u32.u64 %0, t; }"
        : "=r"(a) : "l"(p));
    return a;
}

#define LDSM4(r, addr) \
    asm volatile("ldmatrix.sync.aligned.m8n8.x4.shared.b16 {%0,%1,%2,%3}, [%4];" \
        : "=r"((r)[0]), "=r"((r)[1]), "=r"((r)[2]), "=r"((r)[3]) : "r"(addr))
#define LDSM4T(r, addr) \
    asm volatile("ldmatrix.sync.aligned.m8n8.x4.trans.shared.b16 {%0,%1,%2,%3}, [%4];" \
        : "=r"((r)[0]), "=r"((r)[1]), "=r"((r)[2]), "=r"((r)[3]) : "r"(addr))

#define MMA_BF16(d, a, b0v, b1v) \
    asm volatile("mma.sync.aligned.m16n8k16.row.col.f32.bf16.bf16.f32 " \
        "{%0,%1,%2,%3}, {%4,%5,%6,%7}, {%8,%9}, {%0,%1,%2,%3};" \
        : "+f"((d)[0]), "+f"((d)[1]), "+f"((d)[2]), "+f"((d)[3]) \
        : "r"((a)[0]), "r"((a)[1]), "r"((a)[2]), "r"((a)[3]), "r"(b0v), "r"(b1v))

#define CP_ASYNC16(smem, gmem) \
    asm volatile("cp.async.cg.shared.global [%0], [%1], 16;" :: "r"(smem), "l"(gmem))
#define CP_COMMIT()  asm volatile("cp.async.commit_group;" ::: "memory")
#define CP_WAIT0()   asm volatile("cp.async.wait_group 0;" ::: "memory")
#define CP_WAIT1()   asm volatile("cp.async.wait_group 1;" ::: "memory")

// pack 2 fp32 -> bf16x2 hi + bf16x2 lo (3-split residual), cvt.bf16x2 fast path
__device__ __forceinline__ void splitpack(float x, float y, uint32_t& hi, uint32_t& lo) {
    asm("cvt.rn.bf16x2.f32 %0, %1, %2;" : "=r"(hi) : "f"(y), "f"(x));
    float hx = __uint_as_float(hi << 16);
    float hy = __uint_as_float(hi & 0xffff0000u);
    float lx = x - hx, ly = y - hy;
    asm("cvt.rn.bf16x2.f32 %0, %1, %2;" : "=r"(lo) : "f"(ly), "f"(lx));
}

// ---------------------------------------------------------------------------
// merged fp32 -> (bf16 hi, lo) split. 8 float4 per thread (MLP=8).
// blocks [0,384) = X (8192 floats each); then 4 x 72 = W slots.
// ---------------------------------------------------------------------------
__global__ void __launch_bounds__(256) split_all_kernel(
    const float* __restrict__ X,
    const float* __restrict__ qw, const float* __restrict__ kw,
    const float* __restrict__ vw, const float* __restrict__ ow)
{
    const int bid = blockIdx.x;
    const float* src;
    __nv_bfloat16 *dhi, *dlo;
    size_t off;
    if (bid < 384) {
        src = X; dhi = g_Xhi; dlo = g_Xlo;
        off = (size_t)bid * 8192;
    } else {
        int r = bid - 384;
        int slot = r / 72, rb = r % 72;
        src = (slot == 0) ? qw : (slot == 1) ? kw : (slot == 2) ? vw : ow;
        dhi = g_Whi + (size_t)slot * EE * EE;
        dlo = g_Wlo + (size_t)slot * EE * EE;
        off = (size_t)rb * 8192;
    }
    float4 v[8];
    #pragma unroll
    for (int u = 0; u < 8; u++)
        v[u] = *(const float4*)(src + off + u*1024 + threadIdx.x*4);
    #pragma unroll
    for (int u = 0; u < 8; u++) {
        size_t i = off + u*1024 + threadIdx.x*4;
        float xs[4] = {v[u].x, v[u].y, v[u].z, v[u].w};
        #pragma unroll
        for (int j = 0; j < 4; j++) {
            __nv_bfloat16 hv = __float2bfloat16(xs[j]);
            dhi[i+j] = hv;
            dlo[i+j] = __float2bfloat16(xs[j] - __bfloat162float(hv));
        }
    }
}

// ---------------------------------------------------------------------------
// HMMA GEMM: D = A(M,K) @ W(N,K)^T via 3x bf16-split mma.sync, fp32 accum.
// CTA 128x128, 8 warps (2x4), warp tile 64x32, BK=32, 3-stage cp.async
// pipeline, ONE __syncthreads per stage, 2 CTAs/SM.  MMAs ordered term-major
// per A-fragment so same-accumulator reuse distance is 4 (hides HMMA latency).
// ---------------------------------------------------------------------------
#define NS (EE/32)   // 24 K-stages
__global__ void __launch_bounds__(256, 2) gemm_mma_kernel(
    const float* __restrict__ b0p, const float* __restrict__ b1p,
    const float* __restrict__ b2p, float* __restrict__ outp,
    int wslot0, int is_qkv)
{
    extern __shared__ char dsm[];
    const uint32_t sbase = smem_u32(dsm);

    const int tid = threadIdx.x;
    const int wid = tid >> 5, lane = tid & 31;
    const int warp_m = wid & 1, warp_n = wid >> 1;
    const int m0w = warp_m * 64, n0w = warp_n * 32;

    const int z = is_qkv ? blockIdx.z : 0;
    const size_t woff = (size_t)(wslot0 + z) * EE * EE;
    const float* bias = (z == 0) ? b0p : (z == 1) ? b1p : b2p;
    const float scale = (is_qkv && z == 0) ? SCALING : 1.0f;
    __nv_bfloat16* outHi = (z == 0) ? g_Qhi : (z == 1) ? g_Khi : g_Vhi;
    __nv_bfloat16* outLo = (z == 0) ? g_Qlo : (z == 1) ? g_Klo : g_Vlo;

    const int n0 = blockIdx.x * 128;
    const int m0 = blockIdx.y * 128;

    const __nv_bfloat16* s0 = (is_qkv ? g_Xhi : g_AOhi) + (size_t)m0 * EE;
    const __nv_bfloat16* s1 = (is_qkv ? g_Xlo : g_AOlo) + (size_t)m0 * EE;
    const __nv_bfloat16* s2 = g_Whi + woff + (size_t)n0 * EE;
    const __nv_bfloat16* s3 = g_Wlo + woff + (size_t)n0 * EE;

    const int lrow = tid >> 2;
    const int lch  = tid & 3;
    auto stage_load = [&](int k0, int stg) {
        uint32_t sb = sbase + (uint32_t)stg * 32768u;
        #pragma unroll
        for (int t = 0; t < 4; t++) {
            const __nv_bfloat16* sp = (t==0?s0:t==1?s1:t==2?s2:s3) + k0 + lch*8;
            uint32_t tb = sb + (uint32_t)t * 8192u;
            #pragma unroll
            for (int j = 0; j < 2; j++) {
                int row = lrow + j*64;
                CP_ASYNC16(tb + row*64 + ((lch ^ ((row >> 1) & 3)) << 4),
                           sp + (size_t)row * EE);
            }
        }
        CP_COMMIT();
    };

    const int l7 = lane & 7;
    const int arow_sw = (lane >> 1) & 3;
    const int brow7 = l7 + ((lane >> 4) << 3);
    const int brow_sw = (brow7 >> 1) & 3;
    uint32_t aoff[4], boff[2];
    #pragma unroll
    for (int t = 0; t < 4; t++)
        aoff[t] = (uint32_t)(m0w + t*16 + (lane & 15)) * 64u;
    #pragma unroll
    for (int p = 0; p < 2; p++)
        boff[p] = (uint32_t)(n0w + p*16 + brow7) * 64u;
    const int achk = lane >> 4;
    const int bchk = (lane >> 3) & 1;

    float acc[4][4][4] = {};

    stage_load(0, 0);
    stage_load(32, 1);

    #pragma unroll 1
    for (int s = 0; s < NS; s++) {
        if (s == NS - 1) { CP_WAIT0(); } else { CP_WAIT1(); }
        __syncthreads();
        if (s + 2 < NS) stage_load((s + 2) * 32, (s + 2) % 3);

        const uint32_t stg = sbase + (uint32_t)(s % 3) * 32768u;
        const uint32_t Ahi = stg, Alo = stg + 8192u;
        const uint32_t Bhi = stg + 16384u, Blo = stg + 24576u;

        #pragma unroll
        for (int ks = 0; ks < 2; ks++) {
            const uint32_t asw = (uint32_t)((2*ks + achk) ^ arow_sw) << 4;
            const uint32_t bsw = (uint32_t)((2*ks + bchk) ^ brow_sw) << 4;
            uint32_t Bh[2][4], Bl[2][4];
            #pragma unroll
            for (int p = 0; p < 2; p++) {
                LDSM4(Bh[p], Bhi + boff[p] + bsw);
                LDSM4(Bl[p], Blo + boff[p] + bsw);
            }
            #pragma unroll
            for (int t = 0; t < 4; t++) {
                uint32_t Ah[4], Al[4];
                LDSM4(Ah, Ahi + aoff[t] + asw);
                LDSM4(Al, Alo + aoff[t] + asw);
                // term-major: same acc reused at distance 4
                #pragma unroll
                for (int n = 0; n < 4; n++) {
                    const int p = n >> 1, q = (n & 1) * 2;
                    MMA_BF16(acc[t][n], Ah, Bh[p][q], Bh[p][q+1]);
                }
                #pragma unroll
                for (int n = 0; n < 4; n++) {
                    const int p = n >> 1, q = (n & 1) * 2;
                    MMA_BF16(acc[t][n], Ah, Bl[p][q], Bl[p][q+1]);
                }
                #pragma unroll
                for (int n = 0; n < 4; n++) {
                    const int p = n >> 1, q = (n & 1) * 2;
                    MMA_BF16(acc[t][n], Al, Bh[p][q], Bh[p][q+1]);
                }
            }
        }
    }

    // epilogue
    const int rl = lane >> 2, cl2 = (lane & 3) * 2;
    #pragma unroll
    for (int t = 0; t < 4; t++)
        #pragma unroll
        for (int n = 0; n < 4; n++) {
            const int col = n0 + n0w + n*8 + cl2;
            #pragma unroll
            for (int half = 0; half < 2; half++) {
                const int row = m0 + m0w + t*16 + rl + half*8;
                float ox = (acc[t][n][half*2+0] + bias[col+0]) * scale;
                float oy = (acc[t][n][half*2+1] + bias[col+1]) * scale;
                if (is_qkv) {
                    const int hh = col >> 6, d0 = col & 63;
                    const int bb_ = row >> 10, ss_ = row & 1023;
                    size_t idx = ((size_t)((bb_*HH + hh)*SS + ss_))*DD + d0;
                    uint32_t hi, lo;
                    splitpack(ox, oy, hi, lo);
                    *(uint32_t*)(outHi + idx) = hi;
                    *(uint32_t*)(outLo + idx) = lo;
                } else {
                    float2 o; o.x = ox; o.y = oy;
                    *(float2*)(outp + (size_t)row * EE + col) = o;
                }
            }
        }
}

// ---------------------------------------------------------------------------
// Flash attention on mma.sync bf16 (3-split). CTA = 128 Q rows x (b,h).
// 8 warps, warp = m16 x n64. K/V chunks of 64 rows, double-buffered cp.async.
// MMAs interleaved across accumulator pairs (reuse distance 2).
// ---------------------------------------------------------------------------
__global__ void __launch_bounds__(256, 2) attn_mma_kernel(
    const int* __restrict__ pos_row, const int* __restrict__ pos_col,
    const float* __restrict__ rel_table)
{
    extern __shared__ char dsm[];
    const uint32_t sbase = smem_u32(dsm);
    const uint32_t sQhi = sbase, sQlo = sbase + 16384u;
    int* pk = (int*)(dsm + 98304);

    const int tid = threadIdx.x;
    const int wid = tid >> 5, lane = tid & 31;
    const int l7 = lane & 7;
    const int rl = lane >> 2, cl2 = (lane & 3) * 2;
    const int achk = lane >> 4;
    const int bchk = (lane >> 3) & 1;

    const int q0 = blockIdx.x * 128;
    const int h = blockIdx.y, b = blockIdx.z;
    const size_t hb = (size_t)(b*HH + h) * SS * DD;

    #pragma unroll
    for (int i = 0; i < 4; i++) {
        int s = tid + i*256;
        pk[s] = (pos_row[b*SS + s] << 5) | pos_col[b*SS + s];
    }

    // Q stage: 128 rows x 64 bf16 hi/lo
    {
        const int half = tid >> 7, r = tid & 127;
        const __nv_bfloat16* src = (half ? g_Qlo : g_Qhi) + hb + (size_t)(q0 + r)*DD;
        uint32_t dstrow = (half ? sQlo : sQhi) + (uint32_t)r * 128u;
        #pragma unroll
        for (int ch = 0; ch < 8; ch++)
            CP_ASYNC16(dstrow + ((ch ^ (r & 7)) << 4), src + ch*8);
        CP_COMMIT();
    }

    auto kv_load = [&](int kb, int stg) {
        const int t = tid >> 6, r = tid & 63;
        const __nv_bfloat16* src =
            (t==0 ? g_Khi : t==1 ? g_Klo : t==2 ? g_Vhi : g_Vlo)
            + hb + (size_t)(kb + r)*DD;
        uint32_t dstrow = sbase + 32768u + (uint32_t)stg*32768u
                        + (uint32_t)t*8192u + (uint32_t)r*128u;
        #pragma unroll
        for (int ch = 0; ch < 8; ch++)
            CP_ASYNC16(dstrow + ((ch ^ (r & 7)) << 4), src + ch*8);
        CP_COMMIT();
    };
    kv_load(0, 0);

    CP_WAIT1();
    __syncthreads();

    uint32_t qh[4][4], ql[4][4];
    const uint32_t aq = (uint32_t)(wid*16 + (lane & 15)) * 128u;
    #pragma unroll
    for (int ks = 0; ks < 4; ks++) {
        uint32_t sw = (uint32_t)((2*ks + achk) ^ l7) << 4;
        LDSM4(qh[ks], sQhi + aq + sw);
        LDSM4(ql[ks], sQlo + aq + sw);
    }

    const int rq0 = pk[q0 + wid*16 + rl];
    const int rq1 = pk[q0 + wid*16 + rl + 8];
    const float tb0 = rel_table[0*HH + h];
    const float tb1 = rel_table[1*HH + h];
    const float tb2 = rel_table[2*HH + h];
    const float tb3 = rel_table[3*HH + h];

    float oacc[8][4] = {};
    float m0 = -1e30f, m1 = -1e30f, l0 = 0.f, l1 = 0.f;

    #pragma unroll 1
    for (int kt = 0; kt < SS/64; kt++) {
        CP_WAIT0();
        __syncthreads();
        if (kt + 1 < SS/64) kv_load((kt + 1) * 64, (kt + 1) & 1);

        const uint32_t st  = sbase + 32768u + (uint32_t)(kt & 1) * 32768u;
        const uint32_t Khi = st, Klo = st + 8192u;
        const uint32_t Vhi = st + 16384u, Vlo = st + 24576u;

        // S = Q K^T  (m16 x n64), fp32 accum; interleave the two acc targets
        float sacc[8][4] = {};
        #pragma unroll
        for (int ks = 0; ks < 4; ks++) {
            const uint32_t bsw = (uint32_t)((2*ks + bchk) ^ l7) << 4;
            #pragma unroll
            for (int p = 0; p < 4; p++) {
                const uint32_t bo =
                    (uint32_t)(p*16 + l7 + ((lane >> 4) << 3)) * 128u + bsw;
                uint32_t Bh[4], Bl[4];
                LDSM4(Bh, Khi + bo);
                LDSM4(Bl, Klo + bo);
                MMA_BF16(sacc[2*p],   qh[ks], Bh[0], Bh[1]);
                MMA_BF16(sacc[2*p+1], qh[ks], Bh[2], Bh[3]);
                MMA_BF16(sacc[2*p],   qh[ks], Bl[0], Bl[1]);
                MMA_BF16(sacc[2*p+1], qh[ks], Bl[2], Bl[3]);
                MMA_BF16(sacc[2*p],   ql[ks], Bh[0], Bh[1]);
                MMA_BF16(sacc[2*p+1], ql[ks], Bh[2], Bh[3]);
            }
        }

        // bias
        const int kb = kt * 64;
        #pragma unroll
        for (int t = 0; t < 8; t++) {
            int c0 = kb + t*8 + cl2;
            int rk0 = pk[c0], rk1 = pk[c0 + 1];
            int x;
            x = rq0 ^ rk0; sacc[t][0] += (x < 32) ? (((x & 31) == 0) ? tb3 : tb1)
                                                  : (((x & 31) == 0) ? tb2 : tb0);
            x = rq0 ^ rk1; sacc[t][1] += (x < 32) ? (((x & 31) == 0) ? tb3 : tb1)
                                                  : (((x & 31) == 0) ? tb2 : tb0);
            x = rq1 ^ rk0; sacc[t][2] += (x < 32) ? (((x & 31) == 0) ? tb3 : tb1)
                                                  : (((x & 31) == 0) ? tb2 : tb0);
            x = rq1 ^ rk1; sacc[t][3] += (x < 32) ? (((x & 31) == 0) ? tb3 : tb1)
                                                  : (((x & 31) == 0) ? tb2 : tb0);
        }

        // online softmax (MUFU exp; 4 lanes/row)
        float mx0 = sacc[0][0], mx1 = sacc[0][2];
        #pragma unroll
        for (int t = 0; t < 8; t++) {
            mx0 = fmaxf(mx0, fmaxf(sacc[t][0], sacc[t][1]));
            mx1 = fmaxf(mx1, fmaxf(sacc[t][2], sacc[t][3]));
        }
        mx0 = fmaxf(mx0, __shfl_xor_sync(0xffffffffu, mx0, 1));
        mx0 = fmaxf(mx0, __shfl_xor_sync(0xffffffffu, mx0, 2));
        mx1 = fmaxf(mx1, __shfl_xor_sync(0xffffffffu, mx1, 1));
        mx1 = fmaxf(mx1, __shfl_xor_sync(0xffffffffu, mx1, 2));
        float mn0 = fmaxf(m0, mx0), mn1 = fmaxf(m1, mx1);
        float sc0 = __expf(m0 - mn0), sc1 = __expf(m1 - mn1);
        m0 = mn0; m1 = mn1;
        float rs0 = 0.f, rs1 = 0.f;
        #pragma unroll
        for (int t = 0; t < 8; t++) {
            sacc[t][0] = __expf(sacc[t][0] - mn0);
            sacc[t][1] = __expf(sacc[t][1] - mn0);
            sacc[t][2] = __expf(sacc[t][2] - mn1);
            sacc[t][3] = __expf(sacc[t][3] - mn1);
            rs0 += sacc[t][0] + sacc[t][1];
            rs1 += sacc[t][2] + sacc[t][3];
        }
        rs0 += __shfl_xor_sync(0xffffffffu, rs0, 1);
        rs0 += __shfl_xor_sync(0xffffffffu, rs0, 2);
        rs1 += __shfl_xor_sync(0xffffffffu, rs1, 1);
        rs1 += __shfl_xor_sync(0xffffffffu, rs1, 2);
        l0 = l0 * sc0 + rs0;
        l1 = l1 * sc1 + rs1;
        #pragma unroll
        for (int t = 0; t < 8; t++) {
            oacc[t][0] *= sc0; oacc[t][1] *= sc0;
            oacc[t][2] *= sc1; oacc[t][3] *= sc1;
        }

        // O += P V : P fragments straight from sacc (hi/lo split)
        #pragma unroll
        for (int ks = 0; ks < 4; ks++) {
            uint32_t ph[4], pl[4];
            splitpack(sacc[2*ks][0],   sacc[2*ks][1],   ph[0], pl[0]);
            splitpack(sacc[2*ks][2],   sacc[2*ks][3],   ph[1], pl[1]);
            splitpack(sacc[2*ks+1][0], sacc[2*ks+1][1], ph[2], pl[2]);
            splitpack(sacc[2*ks+1][2], sacc[2*ks+1][3], ph[3], pl[3]);
            const uint32_t vr =
                (uint32_t)(ks*16 + l7 + (((lane >> 3) & 1) << 3)) * 128u;
            #pragma unroll
            for (int p = 0; p < 4; p++) {
                const uint32_t vsw = (uint32_t)((2*p + achk) ^ l7) << 4;
                uint32_t Vh[4], Vl[4];
                LDSM4T(Vh, Vhi + vr + vsw);
                LDSM4T(Vl, Vlo + vr + vsw);
                MMA_BF16(oacc[2*p],   ph, Vh[0], Vh[1]);
                MMA_BF16(oacc[2*p+1], ph, Vh[2], Vh[3]);
                MMA_BF16(oacc[2*p],   ph, Vl[0], Vl[1]);
                MMA_BF16(oacc[2*p+1], ph, Vl[2], Vl[3]);
                MMA_BF16(oacc[2*p],   pl, Vh[0], Vh[1]);
                MMA_BF16(oacc[2*p+1], pl, Vh[2], Vh[3]);
            }
        }
    }

    // epilogue: normalize, emit bf16 hi/lo AO at [B,S,E] (e = h*64+d)
    const float inv0 = 1.0f / l0, inv1 = 1.0f / l1;
    const int qrow0 = q0 + wid*16 + rl;
    #pragma unroll
    for (int t = 0; t < 8; t++) {
        const int e = h*64 + t*8 + cl2;
        size_t i0 = (size_t)(b*SS + qrow0) * EE + e;
        size_t i1 = (size_t)(b*SS + qrow0 + 8) * EE + e;
        uint32_t hi, lo;
        splitpack(oacc[t][0] * inv0, oacc[t][1] * inv0, hi, lo);
        *(uint32_t*)(g_AOhi + i0) = hi;
        *(uint32_t*)(g_AOlo + i0) = lo;
        splitpack(oacc[t][2] * inv1, oacc[t][3] * inv1, hi, lo);
        *(uint32_t*)(g_AOhi + i1) = hi;
        *(uint32_t*)(g_AOlo + i1) = lo;
    }
}

// ---------------------------------------------------------------------------
extern "C" void kernel_launch(void* const* d_in, const int* in_sizes, int n_in,
                              void* d_out, int out_size) {
    const float* X  = (const float*)d_in[0];
    const int*   pr = (const int*)  d_in[1];
    const int*   pc = (const int*)  d_in[2];
    const float* qw = (const float*)d_in[3];
    const float* qb = (const float*)d_in[4];
    const float* kw = (const float*)d_in[5];
    const float* kb = (const float*)d_in[6];
    const float* vw = (const float*)d_in[7];
    const float* vb = (const float*)d_in[8];
    const float* ow = (const float*)d_in[9];
    const float* ob = (const float*)d_in[10];
    const float* rt = (const float*)d_in[11];
    float* out = (float*)d_out;

    const int DSMEM_G = 3 * 32768;
    cudaFuncSetAttribute(gemm_mma_kernel,
                         cudaFuncAttributeMaxDynamicSharedMemorySize, DSMEM_G);
    const int DSMEM_A = 32768 + 2*32768 + 4096;    // 102400
    cudaFuncSetAttribute(attn_mma_kernel,
                         cudaFuncAttributeMaxDynamicSharedMemorySize, DSMEM_A);

    split_all_kernel<<<384 + 4*72, 256>>>(X, qw, kw, vw, ow);

    dim3 g1(EE/128, MT/128, 3);
    gemm_mma_kernel<<<g1, 256, DSMEM_G>>>(qb, kb, vb, nullptr, 0, 1);

    dim3 g2(SS/128, HH, BB);
    attn_mma_kernel<<<g2, 256, DSMEM_A>>>(pr, pc, rt);

    dim3 g3(EE/128, MT/128, 1);
    gemm_mma_kernel<<<g3, 256, DSMEM_G>>>(ob, ob, ob, out, 3, 0);
}